// round 12
// baseline (speedup 1.0000x reference)
#include <cuda_runtime.h>

// CrossAttentionConditionInjection — analytic collapse, ONE kernel:
// concurrent Wv+Wo reads (R11 proved 2 streams => 1412 GB/s vs 750 single),
// Wo staged in SMEM (only in-launch storage survives; L2 carry across
// kernels was falsified in R11), one grid barrier, then broadcast.
//
// Math: K/V come from one condition token broadcast across seq => softmax
// weights are exactly 1/S (S=2048 pow2) => attn == v1.
//   out[b,s,:] = Wo @ (Wv @ cond[b] + bv) + bo   (same vector for every s)

#define BDIM 1024
#define NB   2
#define NS   2048
#define GRID 128          // 1 block/SM on 148 SMs -> co-resident, barrier-safe
#define TPB  1024
#define WO_SMEM_BYTES (16 * BDIM * 4)   // 16 rows x 4KB = 64KB dynamic smem

__device__ float    g_v1[NB * BDIM];
__device__ unsigned g_bar = 0;          // monotonic ticket counter (replay-safe)

__device__ __forceinline__ void grid_sync() {
    __syncthreads();
    if (threadIdx.x == 0) {
        __threadfence();                                // publish v1
        unsigned ticket = atomicAdd(&g_bar, 1u);
        unsigned target = (ticket / GRID + 1u) * GRID;
        while (atomicAdd(&g_bar, 0u) < target)
            __nanosleep(64);
        __threadfence();                                // acquire all v1
    }
    __syncthreads();
}

__global__ void __launch_bounds__(TPB, 1)
fused_kernel(const float* __restrict__ Wv, const float* __restrict__ cond,
             const float* __restrict__ bv, const float* __restrict__ Wo,
             const float* __restrict__ bo, float4* __restrict__ out) {
    extern __shared__ float4 s_wo4[];           // [16][256] float4 = 64KB
    __shared__ float s_o1f[16];

    const int warp = threadIdx.x >> 5;
    const int lane = threadIdx.x & 31;
    const int g    = blockIdx.x;
    const int t0   = g * 16;                    // this block's 16 v1 rows
    const int b    = g >> 6;
    const int d0   = (g & 63) * 16;             // this block's 16 o1 rows

    // ---- Phase 1: two concurrent 4MB read streams (proven 1.4 TB/s) ----
    if (warp < 16) {
        // v1 row t = t0+warp: dot(Wv[d,:], cond[b,:]) + bv[d]
        int t = t0 + warp;
        int d = t & (BDIM - 1);
        const float4* W4 = reinterpret_cast<const float4*>(Wv + (size_t)d * BDIM);
        const float4* x4 = reinterpret_cast<const float4*>(cond + (size_t)b * BDIM);
        float sum = 0.f;
#pragma unroll
        for (int i = 0; i < 8; ++i) {
            float4 wv = W4[lane + i * 32];
            float4 xv = x4[lane + i * 32];
            sum += wv.x * xv.x + wv.y * xv.y + wv.z * xv.z + wv.w * xv.w;
        }
#pragma unroll
        for (int off = 16; off; off >>= 1)
            sum += __shfl_xor_sync(0xffffffffu, sum, off);
        if (lane == 0) g_v1[t] = sum + bv[d];
    } else {
        // Stage Wo row (d0 + warp-16) into SMEM: 8 float4 per lane.
        int q = warp - 16;
        int r = d0 + q;
        const float4* W4 = reinterpret_cast<const float4*>(Wo + (size_t)r * BDIM);
#pragma unroll
        for (int i = 0; i < 8; ++i)
            s_wo4[q * 256 + lane + i * 32] = W4[lane + i * 32];
    }

    grid_sync();                                // all v1 published

    // ---- Phase 2: o1 rows from SMEM-resident Wo + 8KB v1 ----
    if (warp < 16) {
        int r = d0 + warp;
        const float4* v4 = reinterpret_cast<const float4*>(g_v1 + (size_t)b * BDIM);
        float sum = 0.f;
#pragma unroll
        for (int i = 0; i < 8; ++i) {
            float4 wv = s_wo4[warp * 256 + lane + i * 32];
            float4 xv = v4[lane + i * 32];
            sum += wv.x * xv.x + wv.y * xv.y + wv.z * xv.z + wv.w * xv.w;
        }
#pragma unroll
        for (int off = 16; off; off >>= 1)
            sum += __shfl_xor_sync(0xffffffffu, sum, off);
        if (lane == 0) s_o1f[warp] = sum + bo[r];
    }
    __syncthreads();

    // ---- Phase 3: broadcast block's 64B chunk across all 2048 s ----
    const float4* s_o1 = reinterpret_cast<const float4*>(s_o1f);
    float4 v0 = s_o1[0], v1c = s_o1[1], v2 = s_o1[2], v3 = s_o1[3];
    size_t base = ((size_t)b * NS) * (BDIM / 4) + (d0 >> 2);
#pragma unroll
    for (int k = 0; k < 8; ++k) {               // 8192 (s,c) pairs / 1024 thr
        int i = k * TPB + threadIdx.x;
        int s = i >> 2;
        int c = i & 3;
        float4 val = (c == 0) ? v0 : (c == 1) ? v1c : (c == 2) ? v2 : v3;
        __stcs(out + base + (size_t)s * (BDIM / 4) + c, val);
    }
}

extern "C" void kernel_launch(void* const* d_in, const int* in_sizes, int n_in,
                              void* d_out, int out_size) {
    // metadata order: hidden_states, condition, Wq, bq, Wk, bk, Wv, bv, Wo, bo
    const float* cond = (const float*)d_in[1];
    const float* Wv   = (const float*)d_in[6];
    const float* bv   = (const float*)d_in[7];
    const float* Wo   = (const float*)d_in[8];
    const float* bo   = (const float*)d_in[9];

    // Opt-in to 64KB dynamic smem (idempotent; harmless on repeat calls).
    static int attr_done = 0;
    if (!attr_done) {
        cudaFuncSetAttribute(fused_kernel,
                             cudaFuncAttributeMaxDynamicSharedMemorySize,
                             WO_SMEM_BYTES);
        attr_done = 1;
    }
    fused_kernel<<<GRID, TPB, WO_SMEM_BYTES>>>(Wv, cond, bv, Wo, bo,
                                               (float4*)d_out);
}